// round 4
// baseline (speedup 1.0000x reference)
#include <cuda_runtime.h>
#include <math.h>

// A[b,i,j] = softmax_i(s_i + s_j + bias) = exp(s_i)/sum_i' exp(s_i')
// (s_j and bias cancel under softmax over axis=1). Output row (b,i,:) is a
// constant p[b,i] broadcast N wide.
//
// Single persistent kernel, 148 co-resident blocks:
//   phase 1: e=exp(h.w) for this block's rows -> smem; per-batch partials
//   grid barrier (monotonic counter, graph-replay safe)
//   inv[b] reduced redundantly per block in fixed order (deterministic)
//   phase 2: broadcast fill (HBM-write bound)

#define GRID     148
#define NTHR     1024
#define MAX_B    8
#define MAX_RPB  256          // max rows per block (BN <= GRID*MAX_RPB)

__device__ float    g_part[GRID * MAX_B];
__device__ unsigned g_ctr;    // monotonic arrival counter (never reset)

__global__ void __launch_bounds__(NTHR)
fused_kernel(const float* __restrict__ h,
             const float* __restrict__ w,
             float4* __restrict__ out,
             int BN, int N, int B, int D4) {
    __shared__ float e_s[MAX_RPB];
    __shared__ float part_s[32 * MAX_B];
    __shared__ float inv_s[MAX_B];

    const int tid  = threadIdx.x;
    const int warp = tid >> 5;
    const int lane = tid & 31;
    const int bid  = blockIdx.x;
    const int N4   = N >> 2;

    // zero per-warp partials
    if (tid < 32 * MAX_B) part_s[tid] = 0.0f;
    __syncthreads();

    // w (1KB) in registers
    const float4* wv = reinterpret_cast<const float4*>(w);
    float4 b0, b1;
    if (D4 == 64) { b0 = __ldg(wv + lane); b1 = __ldg(wv + lane + 32); }

    // ---- phase 1: dot + exp for this block's rows (row = bid + GRID*idx) ----
    for (int idx = warp; ; idx += 32) {
        int row = bid + GRID * idx;
        if (row >= BN) break;
        float acc;
        if (D4 == 64) {
            const float4* hr = reinterpret_cast<const float4*>(h) + (size_t)row * 64;
            float4 a0 = __ldcs(hr + lane);
            float4 a1 = __ldcs(hr + lane + 32);
            acc = a0.x * b0.x + a0.y * b0.y + a0.z * b0.z + a0.w * b0.w
                + a1.x * b1.x + a1.y * b1.y + a1.z * b1.z + a1.w * b1.w;
        } else {
            const float4* hr = reinterpret_cast<const float4*>(h) + (size_t)row * D4;
            acc = 0.0f;
            for (int c = lane; c < D4; c += 32) {
                float4 a = __ldcs(hr + c);
                float4 bb = __ldg(wv + c);
                acc += a.x * bb.x + a.y * bb.y + a.z * bb.z + a.w * bb.w;
            }
        }
        #pragma unroll
        for (int o = 16; o; o >>= 1)
            acc += __shfl_xor_sync(0xFFFFFFFFu, acc, o);
        if (lane == 0) {
            float ev = __expf(acc);
            e_s[idx] = ev;
            part_s[warp * MAX_B + (row / N)] += ev;   // sequential per warp: deterministic
        }
    }
    __syncthreads();

    // block-level per-batch partials (fixed order) -> global
    if (tid < B) {
        float p = 0.0f;
        #pragma unroll 8
        for (int wi = 0; wi < 32; wi++) p += part_s[wi * MAX_B + tid];
        g_part[bid * MAX_B + tid] = p;
    }
    __threadfence();
    __syncthreads();

    // ---- grid barrier (monotonic, graph-replay safe) ----
    if (tid == 0) {
        unsigned arrival = atomicAdd(&g_ctr, 1u);
        unsigned target  = arrival - (arrival % GRID) + GRID;
        while ((int)(*(volatile unsigned*)&g_ctr - target) < 0) { }
    }
    __syncthreads();
    __threadfence();

    // every block redundantly reduces all partials in FIXED order -> inv[b]
    if (tid < B) {
        float sum = 0.0f;
        for (int i = 0; i < GRID; i++) sum += g_part[i * MAX_B + tid];
        inv_s[tid] = 1.0f / sum;
    }
    __syncthreads();

    // ---- phase 2: broadcast fill (HBM-write bound) ----
    for (int idx = 0; ; idx++) {
        int row = bid + GRID * idx;
        if (row >= BN) break;
        float v = e_s[idx] * inv_s[row / N];
        float4 v4 = make_float4(v, v, v, v);
        float4* o = out + (size_t)row * N4;
        for (int c = tid; c < N4; c += NTHR)
            __stcs(&o[c], v4);
    }
}

extern "C" void kernel_launch(void* const* d_in, const int* in_sizes, int n_in,
                              void* d_out, int out_size) {
    const float* h = (const float*)d_in[0];
    const float* w = (const float*)d_in[1];
    // d_in[2] (bias) cancels in the softmax over axis=1 -> unused.

    int D  = in_sizes[1];                       // 256
    int BN = in_sizes[0] / D;                   // B*N = 16384
    int N  = (int)((long long)out_size / BN);   // 4096
    int B  = BN / N;                            // 4

    fused_kernel<<<GRID, NTHR>>>(h, w, (float4*)d_out, BN, N, B, D >> 2);
}

// round 5
// speedup vs baseline: 1.0869x; 1.0869x over previous
#include <cuda_runtime.h>
#include <math.h>

// A[b,i,j] = softmax_i(s_i + s_j + bias) = exp(s_i)/sum_i' exp(s_i')
// (s_j and bias cancel under softmax over axis=1). Output row (b,i,:) is a
// constant p[b,i] broadcast N wide.
//
// Single persistent kernel, 148 co-resident blocks:
//   phase 1: e=exp(h.w) for this block's rows -> smem; per-batch partials
//   grid barrier (monotonic counter, graph-replay safe)
//   inv[b] reduced redundantly per block, warp-per-batch, fixed order
//   precompute v_s[k] once per row (kills the R4 ALU bottleneck)
//   phase 2: lean broadcast fill: LDS + splat + STG.128 + pointer add only

#define GRID     148
#define NTHR     1024
#define NWARP    (NTHR >> 5)
#define MAX_B    8
#define MAX_RPB  128          // max rows per block (BN <= GRID*MAX_RPB)

__device__ float    g_part[GRID * MAX_B];
__device__ unsigned g_ctr;    // monotonic arrival counter (never reset)

__global__ void __launch_bounds__(NTHR)
fused_kernel(const float* __restrict__ h,
             const float* __restrict__ w,
             float4* __restrict__ out,
             int BN, int N, int B, int D4) {
    __shared__ float e_s[MAX_RPB];
    __shared__ float v_s[MAX_RPB];
    __shared__ float part_s[NWARP * MAX_B];
    __shared__ float inv_s[MAX_B];

    const int tid  = threadIdx.x;
    const int warp = tid >> 5;
    const int lane = tid & 31;
    const int bid  = blockIdx.x;
    const int N4   = N >> 2;

    // zero per-warp per-batch partials
    if (tid < NWARP * MAX_B) part_s[tid] = 0.0f;
    __syncthreads();

    // w (1KB) in registers
    const float4* wv = reinterpret_cast<const float4*>(w);
    float4 b0, b1;
    if (D4 == 64) { b0 = __ldg(wv + lane); b1 = __ldg(wv + lane + 32); }

    // ---- phase 1: dot + exp for this block's rows (row = bid + GRID*idx) ----
    for (int idx = warp; bid + GRID * idx < BN; idx += NWARP) {
        int row = bid + GRID * idx;
        float acc;
        if (D4 == 64) {
            const float4* hr = reinterpret_cast<const float4*>(h) + (size_t)row * 64;
            float4 a0 = __ldcs(hr + lane);
            float4 a1 = __ldcs(hr + lane + 32);
            acc = a0.x * b0.x + a0.y * b0.y + a0.z * b0.z + a0.w * b0.w
                + a1.x * b1.x + a1.y * b1.y + a1.z * b1.z + a1.w * b1.w;
        } else {
            const float4* hr = reinterpret_cast<const float4*>(h) + (size_t)row * D4;
            acc = 0.0f;
            for (int c = lane; c < D4; c += 32) {
                float4 a  = __ldcs(hr + c);
                float4 bb = __ldg(wv + c);
                acc += a.x * bb.x + a.y * bb.y + a.z * bb.z + a.w * bb.w;
            }
        }
        #pragma unroll
        for (int o = 16; o; o >>= 1)
            acc += __shfl_xor_sync(0xFFFFFFFFu, acc, o);
        if (lane == 0) {
            float ev = __expf(acc);
            e_s[idx] = ev;
            part_s[warp * MAX_B + (row / N)] += ev;   // single lane, sequential: deterministic
        }
    }
    __syncthreads();

    // block-level per-batch partials (fixed order) -> global
    if (tid < B) {
        float p = 0.0f;
        #pragma unroll
        for (int wi = 0; wi < NWARP; wi++) p += part_s[wi * MAX_B + tid];
        g_part[bid * MAX_B + tid] = p;
    }
    __threadfence();
    __syncthreads();

    // ---- grid barrier (monotonic, graph-replay safe) ----
    if (tid == 0) {
        unsigned arrival = atomicAdd(&g_ctr, 1u);
        unsigned target  = arrival - (arrival % GRID) + GRID;
        while ((int)(*(volatile unsigned*)&g_ctr - target) < 0) { }
    }
    __syncthreads();
    __threadfence();

    // warp-per-batch redundant reduce, FIXED lane order -> deterministic
    if (warp < B) {
        float sum = 0.0f;
        for (int i = lane; i < GRID; i += 32)
            sum += g_part[i * MAX_B + warp];
        #pragma unroll
        for (int o = 16; o; o >>= 1)
            sum += __shfl_xor_sync(0xFFFFFFFFu, sum, o);
        if (lane == 0) inv_s[warp] = 1.0f / sum;
    }
    __syncthreads();

    // precompute v per row ONCE (div + mul here, not in the fill loop)
    int nrows = (bid < BN) ? ((BN - 1 - bid) / GRID + 1) : 0;
    if (tid < nrows)
        v_s[tid] = e_s[tid] * inv_s[(bid + GRID * tid) / N];
    __syncthreads();

    // ---- phase 2: lean broadcast fill (HBM-write bound) ----
    const size_t stride = (size_t)GRID * N4;
    float4* o = out + (size_t)bid * N4;
    for (int k = 0; k < nrows; k++) {
        float v = v_s[k];
        float4 v4 = make_float4(v, v, v, v);
        for (int c = tid; c < N4; c += NTHR)
            __stcs(o + c, v4);
        o += stride;
    }
}

extern "C" void kernel_launch(void* const* d_in, const int* in_sizes, int n_in,
                              void* d_out, int out_size) {
    const float* h = (const float*)d_in[0];
    const float* w = (const float*)d_in[1];
    // d_in[2] (bias) cancels in the softmax over axis=1 -> unused.

    int D  = in_sizes[1];                       // 256
    int BN = in_sizes[0] / D;                   // B*N = 16384
    int N  = (int)((long long)out_size / BN);   // 4096
    int B  = BN / N;                            // 4

    fused_kernel<<<GRID, NTHR>>>(h, w, (float4*)d_out, BN, N, B, D >> 2);
}

// round 6
// speedup vs baseline: 1.2201x; 1.1225x over previous
#include <cuda_runtime.h>
#include <math.h>

// A[b,i,j] = softmax_i(s_i + s_j + bias) = exp(s_i)/sum_i' exp(s_i')
// (s_j and bias cancel under softmax over axis=1). Output row (b,i,:) is a
// constant p[b,i] broadcast N wide.
//
// Two launches only:
//  K1: e=exp(h.w) (4 rows/warp, MLP=8) + per-block partial sums (no atomics)
//  K2: fill — each block reduces its batch's 128 partials itself (fixed order,
//      identical across blocks -> deterministic), then streams __stwt stores.
//      Write-through leaves L2 clean so next replay's K1 reads don't contend
//      with dirty-line writeback.

#define MAX_BN   16384    // B*N for B=4, N=4096
#define K1_BLOCKS 512
#define K1_THREADS 256    // 8 warps * 4 rows = 32 rows/block
#define ROWS_PER_WARP 4
#define MAX_PART  1024

__device__ float g_e[MAX_BN];        // exp(s)
__device__ float g_part[MAX_PART];   // per-block partial sums (block b covers one batch slice)

// ---- K1: dot + exp + block partial sum ----
__global__ void __launch_bounds__(K1_THREADS)
dot_exp_kernel(const float* __restrict__ h,
               const float* __restrict__ w,
               int BN, int D4) {
    __shared__ float s_warp[K1_THREADS / 32];

    const int warp = threadIdx.x >> 5;
    const int lane = threadIdx.x & 31;
    const int row0 = blockIdx.x * (K1_THREADS / 32 * ROWS_PER_WARP) + warp * ROWS_PER_WARP;

    const float4* wv = reinterpret_cast<const float4*>(w);
    float e_sum = 0.0f;

    if (D4 == 64 && row0 + ROWS_PER_WARP <= BN) {
        float4 b0 = __ldg(wv + lane);
        float4 b1 = __ldg(wv + lane + 32);
        // batch all 8 h loads up front (MLP=8)
        float4 a0[ROWS_PER_WARP], a1[ROWS_PER_WARP];
        #pragma unroll
        for (int r = 0; r < ROWS_PER_WARP; r++) {
            const float4* hr = reinterpret_cast<const float4*>(h) + (size_t)(row0 + r) * 64;
            a0[r] = __ldg(hr + lane);
            a1[r] = __ldg(hr + lane + 32);
        }
        #pragma unroll
        for (int r = 0; r < ROWS_PER_WARP; r++) {
            float acc = a0[r].x * b0.x + a0[r].y * b0.y + a0[r].z * b0.z + a0[r].w * b0.w
                      + a1[r].x * b1.x + a1[r].y * b1.y + a1[r].z * b1.z + a1[r].w * b1.w;
            #pragma unroll
            for (int o = 16; o; o >>= 1)
                acc += __shfl_xor_sync(0xFFFFFFFFu, acc, o);
            float ev = __expf(acc);
            if (lane == 0) {
                g_e[row0 + r] = ev;
                e_sum += ev;                 // sequential in r: deterministic
            }
        }
    } else {
        for (int r = 0; r < ROWS_PER_WARP; r++) {
            int row = row0 + r;
            if (row >= BN) break;
            const float4* hr = reinterpret_cast<const float4*>(h) + (size_t)row * D4;
            float acc = 0.0f;
            for (int c = lane; c < D4; c += 32) {
                float4 a = __ldg(hr + c);
                float4 b = __ldg(wv + c);
                acc += a.x * b.x + a.y * b.y + a.z * b.z + a.w * b.w;
            }
            #pragma unroll
            for (int o = 16; o; o >>= 1)
                acc += __shfl_xor_sync(0xFFFFFFFFu, acc, o);
            if (lane == 0) {
                float ev = __expf(acc);
                g_e[row] = ev;
                e_sum += ev;
            }
        }
    }

    if (lane == 0) s_warp[warp] = e_sum;
    __syncthreads();
    if (threadIdx.x == 0) {
        float p = 0.0f;
        #pragma unroll
        for (int i = 0; i < K1_THREADS / 32; i++) p += s_warp[i];  // fixed order
        g_part[blockIdx.x] = p;
    }
}

// ---- K2: per-block inv reduce + broadcast fill (proven R1 shape) ----
__global__ void __launch_bounds__(256)
fill_kernel(const float* __restrict__ e,
            float4* __restrict__ out,
            int N4, int parts_per_batch) {
    __shared__ float inv_s;

    // warp 0: reduce this batch's partials in FIXED order (identical on every
    // block of the batch -> deterministic & consistent)
    if (threadIdx.x < 32) {
        int lane = threadIdx.x;
        int base = blockIdx.y * parts_per_batch;
        int per_lane = parts_per_batch >> 5;          // 128/32 = 4
        float p = 0.0f;
        for (int k = 0; k < per_lane; k++)
            p += g_part[base + lane * per_lane + k];  // sequential per lane
        #pragma unroll
        for (int o = 16; o; o >>= 1)
            p += __shfl_xor_sync(0xFFFFFFFFu, p, o);
        if (lane == 0) inv_s = 1.0f / p;
    }
    __syncthreads();

    size_t row = (size_t)blockIdx.y * gridDim.x + blockIdx.x;
    float v = __ldg(&e[row]) * inv_s;
    float4 v4 = make_float4(v, v, v, v);
    float4* o = out + row * (size_t)N4;
    #pragma unroll 4
    for (int c = threadIdx.x; c < N4; c += blockDim.x)
        __stwt(&o[c], v4);     // write-through: L2 stays clean for next replay
}

extern "C" void kernel_launch(void* const* d_in, const int* in_sizes, int n_in,
                              void* d_out, int out_size) {
    const float* h = (const float*)d_in[0];
    const float* w = (const float*)d_in[1];
    // d_in[2] (bias) cancels in the softmax over axis=1 -> unused.

    int D  = in_sizes[1];                       // 256
    int BN = in_sizes[0] / D;                   // B*N = 16384
    int N  = (int)((long long)out_size / BN);   // 4096
    int B  = BN / N;                            // 4

    float* e = nullptr;
    cudaGetSymbolAddress((void**)&e, g_e);

    int rows_per_block = (K1_THREADS / 32) * ROWS_PER_WARP;     // 32
    int k1_blocks = (BN + rows_per_block - 1) / rows_per_block; // 512
    dot_exp_kernel<<<k1_blocks, K1_THREADS>>>(h, w, BN, D >> 2);

    int parts_per_batch = k1_blocks / B;                        // 128
    dim3 grid(N, B);
    fill_kernel<<<grid, 256>>>(e, (float4*)d_out, N >> 2, parts_per_batch);
}

// round 7
// speedup vs baseline: 1.3263x; 1.0871x over previous
#include <cuda_runtime.h>
#include <math.h>

// A[b,i,j] = softmax_i(s_i + s_j + bias) = exp(s_i)/sum_i' exp(s_i')
// (s_j and bias cancel under softmax over axis=1). Output row (b,i,:) is a
// constant p[b,i] broadcast N wide.
//
// Two launches:
//  K1: e=exp(h.w) (4 rows/warp, MLP=8) + per-block partial sums (no atomics)
//  K2: fill — each block reduces its batch's 128 partials itself (fixed order,
//      identical across blocks -> deterministic), then streams __stcs stores.
//      (R6 lesson: __stwt throttles to 4.8 TB/s; __stcs rides L2 write
//      coalescing at ~7 TB/s.)

#define MAX_BN   16384    // B*N for B=4, N=4096
#define K1_THREADS 256    // 8 warps * 4 rows = 32 rows/block
#define ROWS_PER_WARP 4
#define MAX_PART  1024

__device__ float g_e[MAX_BN];        // exp(s)
__device__ float g_part[MAX_PART];   // per-block partial sums

// ---- K1: dot + exp + block partial sum ----
__global__ void __launch_bounds__(K1_THREADS)
dot_exp_kernel(const float* __restrict__ h,
               const float* __restrict__ w,
               int BN, int D4) {
    __shared__ float s_warp[K1_THREADS / 32];

    const int warp = threadIdx.x >> 5;
    const int lane = threadIdx.x & 31;
    const int row0 = blockIdx.x * (K1_THREADS / 32 * ROWS_PER_WARP) + warp * ROWS_PER_WARP;

    const float4* wv = reinterpret_cast<const float4*>(w);
    float e_sum = 0.0f;

    if (D4 == 64 && row0 + ROWS_PER_WARP <= BN) {
        float4 b0 = __ldg(wv + lane);
        float4 b1 = __ldg(wv + lane + 32);
        // batch all 8 h loads up front (MLP=8)
        float4 a0[ROWS_PER_WARP], a1[ROWS_PER_WARP];
        #pragma unroll
        for (int r = 0; r < ROWS_PER_WARP; r++) {
            const float4* hr = reinterpret_cast<const float4*>(h) + (size_t)(row0 + r) * 64;
            a0[r] = __ldg(hr + lane);
            a1[r] = __ldg(hr + lane + 32);
        }
        #pragma unroll
        for (int r = 0; r < ROWS_PER_WARP; r++) {
            float acc = a0[r].x * b0.x + a0[r].y * b0.y + a0[r].z * b0.z + a0[r].w * b0.w
                      + a1[r].x * b1.x + a1[r].y * b1.y + a1[r].z * b1.z + a1[r].w * b1.w;
            #pragma unroll
            for (int o = 16; o; o >>= 1)
                acc += __shfl_xor_sync(0xFFFFFFFFu, acc, o);
            float ev = __expf(acc);
            if (lane == 0) {
                g_e[row0 + r] = ev;
                e_sum += ev;                 // sequential in r: deterministic
            }
        }
    } else {
        for (int r = 0; r < ROWS_PER_WARP; r++) {
            int row = row0 + r;
            if (row >= BN) break;
            const float4* hr = reinterpret_cast<const float4*>(h) + (size_t)row * D4;
            float acc = 0.0f;
            for (int c = lane; c < D4; c += 32) {
                float4 a = __ldg(hr + c);
                float4 b = __ldg(wv + c);
                acc += a.x * b.x + a.y * b.y + a.z * b.z + a.w * b.w;
            }
            #pragma unroll
            for (int o = 16; o; o >>= 1)
                acc += __shfl_xor_sync(0xFFFFFFFFu, acc, o);
            if (lane == 0) {
                float ev = __expf(acc);
                g_e[row] = ev;
                e_sum += ev;
            }
        }
    }

    if (lane == 0) s_warp[warp] = e_sum;
    __syncthreads();
    if (threadIdx.x == 0) {
        float p = 0.0f;
        #pragma unroll
        for (int i = 0; i < K1_THREADS / 32; i++) p += s_warp[i];  // fixed order
        g_part[blockIdx.x] = p;
    }
}

// ---- K2: per-block inv reduce + broadcast fill ----
__global__ void __launch_bounds__(256)
fill_kernel(const float* __restrict__ e,
            float4* __restrict__ out,
            int N4, int parts_per_batch) {
    __shared__ float inv_s;

    // warp 0: reduce this batch's partials in FIXED order (identical on every
    // block of the batch -> deterministic & consistent)
    if (threadIdx.x < 32) {
        int lane = threadIdx.x;
        int base = blockIdx.y * parts_per_batch;
        int per_lane = parts_per_batch >> 5;          // 128/32 = 4
        float p = 0.0f;
        for (int k = 0; k < per_lane; k++)
            p += g_part[base + lane * per_lane + k];  // sequential per lane
        #pragma unroll
        for (int o = 16; o; o >>= 1)
            p += __shfl_xor_sync(0xFFFFFFFFu, p, o);
        if (lane == 0) inv_s = 1.0f / p;
    }
    __syncthreads();

    size_t row = (size_t)blockIdx.y * gridDim.x + blockIdx.x;
    float v = __ldg(&e[row]) * inv_s;
    float4 v4 = make_float4(v, v, v, v);
    float4* o = out + row * (size_t)N4;
    #pragma unroll 4
    for (int c = threadIdx.x; c < N4; c += blockDim.x)
        __stcs(&o[c], v4);     // evict-first streaming store (R1/R6-proven ~7 TB/s)
}

extern "C" void kernel_launch(void* const* d_in, const int* in_sizes, int n_in,
                              void* d_out, int out_size) {
    const float* h = (const float*)d_in[0];
    const float* w = (const float*)d_in[1];
    // d_in[2] (bias) cancels in the softmax over axis=1 -> unused.

    int D  = in_sizes[1];                       // 256
    int BN = in_sizes[0] / D;                   // B*N = 16384
    int N  = (int)((long long)out_size / BN);   // 4096
    int B  = BN / N;                            // 4

    float* e = nullptr;
    cudaGetSymbolAddress((void**)&e, g_e);

    int rows_per_block = (K1_THREADS / 32) * ROWS_PER_WARP;     // 32
    int k1_blocks = (BN + rows_per_block - 1) / rows_per_block; // 512
    dot_exp_kernel<<<k1_blocks, K1_THREADS>>>(h, w, BN, D >> 2);

    int parts_per_batch = k1_blocks / B;                        // 128
    dim3 grid(N, B);
    fill_kernel<<<grid, 256>>>(e, (float4*)d_out, N >> 2, parts_per_batch);
}

// round 8
// speedup vs baseline: 1.3341x; 1.0059x over previous
#include <cuda_runtime.h>
#include <math.h>

// A[b,i,j] = softmax_i(s_i + s_j + bias) = exp(s_i)/sum_i' exp(s_i')
// (s_j and bias cancel under softmax over axis=1). Output row (b,i,:) is a
// constant p[b,i] broadcast N wide.
//
// Two launches:
//  K1: e=exp(h.w) (4 rows/warp, MLP=8) + per-block partial sums (no atomics)
//  K2: fill — 8 rows per block (512 thr): the per-block inv reduce head
//      (R7's 4.8TB/s regression cause) amortizes over 128KB of stores.

#define MAX_BN   16384    // B*N for B=4, N=4096
#define K1_THREADS 256    // 8 warps * 4 rows = 32 rows/block
#define ROWS_PER_WARP 4
#define MAX_PART  1024
#define FILL_ROWS 8       // rows per fill block
#define FILL_THREADS 512

__device__ float g_e[MAX_BN];        // exp(s)
__device__ float g_part[MAX_PART];   // per-block partial sums

// ---- K1: dot + exp + block partial sum ----
__global__ void __launch_bounds__(K1_THREADS)
dot_exp_kernel(const float* __restrict__ h,
               const float* __restrict__ w,
               int BN, int D4) {
    __shared__ float s_warp[K1_THREADS / 32];

    const int warp = threadIdx.x >> 5;
    const int lane = threadIdx.x & 31;
    const int row0 = blockIdx.x * (K1_THREADS / 32 * ROWS_PER_WARP) + warp * ROWS_PER_WARP;

    const float4* wv = reinterpret_cast<const float4*>(w);
    float e_sum = 0.0f;

    if (D4 == 64 && row0 + ROWS_PER_WARP <= BN) {
        float4 b0 = __ldg(wv + lane);
        float4 b1 = __ldg(wv + lane + 32);
        // batch all 8 h loads up front (MLP=8)
        float4 a0[ROWS_PER_WARP], a1[ROWS_PER_WARP];
        #pragma unroll
        for (int r = 0; r < ROWS_PER_WARP; r++) {
            const float4* hr = reinterpret_cast<const float4*>(h) + (size_t)(row0 + r) * 64;
            a0[r] = __ldg(hr + lane);
            a1[r] = __ldg(hr + lane + 32);
        }
        #pragma unroll
        for (int r = 0; r < ROWS_PER_WARP; r++) {
            float acc = a0[r].x * b0.x + a0[r].y * b0.y + a0[r].z * b0.z + a0[r].w * b0.w
                      + a1[r].x * b1.x + a1[r].y * b1.y + a1[r].z * b1.z + a1[r].w * b1.w;
            #pragma unroll
            for (int o = 16; o; o >>= 1)
                acc += __shfl_xor_sync(0xFFFFFFFFu, acc, o);
            float ev = __expf(acc);
            if (lane == 0) {
                g_e[row0 + r] = ev;
                e_sum += ev;                 // sequential in r: deterministic
            }
        }
    } else {
        for (int r = 0; r < ROWS_PER_WARP; r++) {
            int row = row0 + r;
            if (row >= BN) break;
            const float4* hr = reinterpret_cast<const float4*>(h) + (size_t)row * D4;
            float acc = 0.0f;
            for (int c = lane; c < D4; c += 32) {
                float4 a = __ldg(hr + c);
                float4 b = __ldg(wv + c);
                acc += a.x * b.x + a.y * b.y + a.z * b.z + a.w * b.w;
            }
            #pragma unroll
            for (int o = 16; o; o >>= 1)
                acc += __shfl_xor_sync(0xFFFFFFFFu, acc, o);
            if (lane == 0) {
                float ev = __expf(acc);
                g_e[row] = ev;
                e_sum += ev;
            }
        }
    }

    if (lane == 0) s_warp[warp] = e_sum;
    __syncthreads();
    if (threadIdx.x == 0) {
        float p = 0.0f;
        #pragma unroll
        for (int i = 0; i < K1_THREADS / 32; i++) p += s_warp[i];  // fixed order
        g_part[blockIdx.x] = p;
    }
}

// ---- K2: per-block inv reduce (amortized over 8 rows) + broadcast fill ----
__global__ void __launch_bounds__(FILL_THREADS)
fill_kernel(const float* __restrict__ e,
            float4* __restrict__ out,
            int N4, int parts_per_batch) {
    __shared__ float inv_s;
    __shared__ float v_s[FILL_ROWS];

    const int tid = threadIdx.x;

    // warp 0: reduce this batch's partials in FIXED order (identical on every
    // block of the batch -> deterministic & consistent)
    if (tid < 32) {
        int base = blockIdx.y * parts_per_batch;
        int per_lane = parts_per_batch >> 5;          // 128/32 = 4
        float p = 0.0f;
        for (int k = 0; k < per_lane; k++)
            p += g_part[base + tid * per_lane + k];   // sequential per lane
        #pragma unroll
        for (int o = 16; o; o >>= 1)
            p += __shfl_xor_sync(0xFFFFFFFFu, p, o);
        if (tid == 0) inv_s = 1.0f / p;
    }
    __syncthreads();

    size_t row0 = (size_t)blockIdx.y * ((size_t)gridDim.x * FILL_ROWS)
                + (size_t)blockIdx.x * FILL_ROWS;
    if (tid < FILL_ROWS)
        v_s[tid] = __ldg(&e[row0 + tid]) * inv_s;
    __syncthreads();

    float4* o = out + row0 * (size_t)N4;
    #pragma unroll
    for (int c = tid; c < N4; c += FILL_THREADS) {
        #pragma unroll
        for (int r = 0; r < FILL_ROWS; r++) {
            float v = v_s[r];
            __stcs(o + (size_t)r * N4 + c, make_float4(v, v, v, v));
        }
    }
}

extern "C" void kernel_launch(void* const* d_in, const int* in_sizes, int n_in,
                              void* d_out, int out_size) {
    const float* h = (const float*)d_in[0];
    const float* w = (const float*)d_in[1];
    // d_in[2] (bias) cancels in the softmax over axis=1 -> unused.

    int D  = in_sizes[1];                       // 256
    int BN = in_sizes[0] / D;                   // B*N = 16384
    int N  = (int)((long long)out_size / BN);   // 4096
    int B  = BN / N;                            // 4

    float* e = nullptr;
    cudaGetSymbolAddress((void**)&e, g_e);

    int rows_per_block = (K1_THREADS / 32) * ROWS_PER_WARP;     // 32
    int k1_blocks = (BN + rows_per_block - 1) / rows_per_block; // 512
    dot_exp_kernel<<<k1_blocks, K1_THREADS>>>(h, w, BN, D >> 2);

    int parts_per_batch = k1_blocks / B;                        // 128
    dim3 grid(N / FILL_ROWS, B);                                // 512 x 4
    fill_kernel<<<grid, FILL_THREADS>>>(e, (float4*)d_out, N >> 2, parts_per_batch);
}